// round 1
// baseline (speedup 1.0000x reference)
#include <cuda_runtime.h>
#include <cuda_bf16.h>
#include <math.h>

// Problem dims (fixed by the reference)
#define T_STEPS 512
#define BATCH   256
#define DIM     1024   // D == H
#define HID     1024
#define OUTD    5

// Scratch: E = x @ W_in^T + b_in for all timesteps, and ping-pong hidden state.
__device__ float g_E[(size_t)T_STEPS * BATCH * HID];   // 512 MB
__device__ float g_h[2][(size_t)BATCH * HID];

// ---------------------------------------------------------------------------
// Register-tiled fp32 GEMM (NT: A[M,K] row-major, W[N,K] row-major),
// C = epilogue(A @ W^T + bias [+ Eadd, sigmoid]).
// Uses packed fma.rn.f32x2 for 2x fp32 FMA throughput.
// Block: 16x16 threads. Thread computes TM x TN outputs. All dims divisible.
// ---------------------------------------------------------------------------
template<int BM, int BN, int BK, int TM, int TN, bool STEP>
__global__ void gemm_nt_kernel(const float* __restrict__ A,
                               const float* __restrict__ W,
                               const float* __restrict__ bias,
                               const float* __restrict__ Eadd,   // [M,N], only if STEP
                               float* __restrict__ C,
                               int M, int N, int K)
{
    __shared__ __align__(16) float As[BK][BM + 2];
    __shared__ __align__(16) float Bs[BK][BN + 2];

    const int tx  = threadIdx.x;            // 0..15
    const int ty  = threadIdx.y;            // 0..15
    const int tid = ty * 16 + tx;

    const int rowBase = blockIdx.y * BM;
    const int colBase = blockIdx.x * BN;

    unsigned long long acc2[TM][TN / 2];
    #pragma unroll
    for (int i = 0; i < TM; i++)
        #pragma unroll
        for (int j = 0; j < TN / 2; j++)
            acc2[i][j] = 0ull;

    constexpr int AK4 = BK / 4;

    for (int k0 = 0; k0 < K; k0 += BK) {
        // Load A tile (BM x BK), store transposed As[k][m]
        for (int i = tid; i < (BM * BK) / 4; i += 256) {
            int r  = i / AK4;
            int c4 = i % AK4;
            float4 v = *(const float4*)(A + (size_t)(rowBase + r) * K + k0 + c4 * 4);
            As[c4 * 4 + 0][r] = v.x;
            As[c4 * 4 + 1][r] = v.y;
            As[c4 * 4 + 2][r] = v.z;
            As[c4 * 4 + 3][r] = v.w;
        }
        // Load W tile (BN x BK), store transposed Bs[k][n]
        for (int i = tid; i < (BN * BK) / 4; i += 256) {
            int r  = i / AK4;
            int c4 = i % AK4;
            float4 v = *(const float4*)(W + (size_t)(colBase + r) * K + k0 + c4 * 4);
            Bs[c4 * 4 + 0][r] = v.x;
            Bs[c4 * 4 + 1][r] = v.y;
            Bs[c4 * 4 + 2][r] = v.z;
            Bs[c4 * 4 + 3][r] = v.w;
        }
        __syncthreads();

        #pragma unroll
        for (int k = 0; k < BK; k++) {
            float a[TM];
            unsigned long long b2[TN / 2];
            #pragma unroll
            for (int i = 0; i < TM; i++)
                a[i] = As[k][ty * TM + i];
            #pragma unroll
            for (int j = 0; j < TN / 2; j++)
                b2[j] = *(const unsigned long long*)&Bs[k][tx * TN + 2 * j];
            #pragma unroll
            for (int i = 0; i < TM; i++) {
                unsigned long long a2;
                asm("mov.b64 %0, {%1, %1};"
                    : "=l"(a2) : "r"(__float_as_uint(a[i])));
                #pragma unroll
                for (int j = 0; j < TN / 2; j++)
                    asm("fma.rn.f32x2 %0, %1, %2, %0;"
                        : "+l"(acc2[i][j]) : "l"(a2), "l"(b2[j]));
            }
        }
        __syncthreads();
    }

    // Epilogue
    #pragma unroll
    for (int i = 0; i < TM; i++) {
        int m = rowBase + ty * TM + i;
        #pragma unroll
        for (int j = 0; j < TN / 2; j++) {
            int n = colBase + tx * TN + 2 * j;
            unsigned int u0 = (unsigned int)(acc2[i][j] & 0xffffffffull);
            unsigned int u1 = (unsigned int)(acc2[i][j] >> 32);
            float v0 = __uint_as_float(u0) + bias[n];
            float v1 = __uint_as_float(u1) + bias[n + 1];
            if (STEP) {
                float2 e = *(const float2*)(Eadd + (size_t)m * N + n);
                v0 += e.x;
                v1 += e.y;
                v0 = 1.0f / (1.0f + __expf(-v0));
                v1 = 1.0f / (1.0f + __expf(-v1));
            }
            float2 o;
            o.x = v0; o.y = v1;
            *(float2*)(C + (size_t)m * N + n) = o;
        }
    }
}

// ---------------------------------------------------------------------------
// Final head: logits = h @ W_o^T + b_o; out = log_softmax(logits);
// also emit hidden and state (zeros) in the output tuple layout.
// out layout: [B*OUTD] out, then [B*HID] hidden, then [B*HID] state.
// Grid: B blocks of 128 threads.
// ---------------------------------------------------------------------------
__global__ void finalize_kernel(const float* __restrict__ h,
                                const float* __restrict__ W_o,
                                const float* __restrict__ b_o,
                                float* __restrict__ out)
{
    const int b   = blockIdx.x;
    const int tid = threadIdx.x;

    __shared__ float logits[OUTD];

    if (tid < 32) {
        float acc[OUTD];
        #pragma unroll
        for (int o = 0; o < OUTD; o++) acc[o] = 0.0f;
        for (int k = tid; k < HID; k += 32) {
            float hv = h[(size_t)b * HID + k];
            #pragma unroll
            for (int o = 0; o < OUTD; o++)
                acc[o] += hv * W_o[(size_t)o * HID + k];
        }
        #pragma unroll
        for (int o = 0; o < OUTD; o++) {
            float v = acc[o];
            #pragma unroll
            for (int s = 16; s > 0; s >>= 1)
                v += __shfl_xor_sync(0xffffffff, v, s);
            if (tid == 0) logits[o] = v + b_o[o];
        }
    }
    __syncthreads();

    if (tid == 0) {
        float m = logits[0];
        #pragma unroll
        for (int o = 1; o < OUTD; o++) m = fmaxf(m, logits[o]);
        float s = 0.0f;
        #pragma unroll
        for (int o = 0; o < OUTD; o++) s += expf(logits[o] - m);
        float lse = m + logf(s);
        #pragma unroll
        for (int o = 0; o < OUTD; o++)
            out[(size_t)b * OUTD + o] = logits[o] - lse;
    }

    float* hid_out = out + (size_t)BATCH * OUTD;
    float* st_out  = hid_out + (size_t)BATCH * HID;
    for (int k = tid; k < HID; k += blockDim.x) {
        hid_out[(size_t)b * HID + k] = h[(size_t)b * HID + k];
        st_out[(size_t)b * HID + k]  = 0.0f;
    }
}

extern "C" void kernel_launch(void* const* d_in, const int* in_sizes, int n_in,
                              void* d_out, int out_size)
{
    const float* x    = (const float*)d_in[0];  // [T,B,D]
    const float* h0   = (const float*)d_in[1];  // [B,H]
    const float* W_in = (const float*)d_in[3];  // [H,D]
    const float* b_in = (const float*)d_in[4];  // [H]
    const float* W_h  = (const float*)d_in[5];  // [H,H]
    const float* b_h  = (const float*)d_in[6];  // [H]
    const float* W_o  = (const float*)d_in[7];  // [O,H]
    const float* b_o  = (const float*)d_in[8];  // [O]
    float* out = (float*)d_out;

    float* Eptr = nullptr;
    float* hptr = nullptr;
    cudaGetSymbolAddress((void**)&Eptr, g_E);
    cudaGetSymbolAddress((void**)&hptr, g_h);

    dim3 blk(16, 16);

    // 1) E = x @ W_in^T + b_in  : M = T*B = 131072, N = HID, K = DIM
    {
        dim3 grid(HID / 128, (T_STEPS * BATCH) / 128);
        gemm_nt_kernel<128, 128, 16, 8, 8, false><<<grid, blk>>>(
            x, W_in, b_in, nullptr, Eptr, T_STEPS * BATCH, HID, DIM);
    }

    // 2) Recurrence: h = sigmoid(h @ W_h^T + b_h + E_t), 512 sequential steps
    {
        dim3 grid(HID / 64, BATCH / 32);
        for (int t = 0; t < T_STEPS; t++) {
            const float* hin = (t == 0) ? h0 : hptr + ((size_t)((t - 1) & 1)) * BATCH * HID;
            float*       hout = hptr + ((size_t)(t & 1)) * BATCH * HID;
            gemm_nt_kernel<32, 64, 16, 2, 4, true><<<grid, blk>>>(
                hin, W_h, b_h, Eptr + (size_t)t * BATCH * HID, hout, BATCH, HID, HID);
        }
    }

    // 3) Head + output tuple assembly. Final h is g_h[1] (t=511 is odd).
    finalize_kernel<<<BATCH, 128>>>(hptr + (size_t)BATCH * HID, W_o, b_o, out);
}

// round 2
// speedup vs baseline: 1.7405x; 1.7405x over previous
#include <cuda_runtime.h>
#include <cuda_bf16.h>
#include <math.h>

// Problem dims (fixed by the reference)
#define T_STEPS 512
#define BATCH   256
#define DIM     1024   // D == H
#define HID     1024
#define OUTD    5

// Persistent-kernel geometry
#define GRID_P  128       // 32 N-tiles x 4 B-tiles, all co-resident (<=148 SMs)
#define NTILE   32
#define BTILE   64
#define BK      32
#define AS_STR  36        // BK + 4 pad (keeps 16B alignment, breaks conflicts)

// Scratch: E = x @ W_in^T + b_in for all timesteps, ping-pong hidden, barrier.
__device__ float    g_E[(size_t)T_STEPS * BATCH * HID];   // 512 MB
__device__ float    g_h[2][(size_t)BATCH * HID];
__device__ unsigned g_bar[2];   // [0]=arrive, [1]=generation

// ---------------------------------------------------------------------------
// fp32x2 GEMM for the input projection (unchanged from R0, it works):
// C = A @ W^T + bias.  Block 16x16 threads, thread tile TM x TN.
// ---------------------------------------------------------------------------
template<int BM, int BN, int BKT, int TM, int TN>
__global__ void gemm_nt_kernel(const float* __restrict__ A,
                               const float* __restrict__ W,
                               const float* __restrict__ bias,
                               float* __restrict__ C,
                               int M, int N, int K)
{
    __shared__ __align__(16) float As[BKT][BM + 2];
    __shared__ __align__(16) float Bs[BKT][BN + 2];

    const int tx  = threadIdx.x;
    const int ty  = threadIdx.y;
    const int tid = ty * 16 + tx;

    const int rowBase = blockIdx.y * BM;
    const int colBase = blockIdx.x * BN;

    unsigned long long acc2[TM][TN / 2];
    #pragma unroll
    for (int i = 0; i < TM; i++)
        #pragma unroll
        for (int j = 0; j < TN / 2; j++)
            acc2[i][j] = 0ull;

    constexpr int AK4 = BKT / 4;

    for (int k0 = 0; k0 < K; k0 += BKT) {
        for (int i = tid; i < (BM * BKT) / 4; i += 256) {
            int r  = i / AK4;
            int c4 = i % AK4;
            float4 v = *(const float4*)(A + (size_t)(rowBase + r) * K + k0 + c4 * 4);
            As[c4 * 4 + 0][r] = v.x;
            As[c4 * 4 + 1][r] = v.y;
            As[c4 * 4 + 2][r] = v.z;
            As[c4 * 4 + 3][r] = v.w;
        }
        for (int i = tid; i < (BN * BKT) / 4; i += 256) {
            int r  = i / AK4;
            int c4 = i % AK4;
            float4 v = *(const float4*)(W + (size_t)(colBase + r) * K + k0 + c4 * 4);
            Bs[c4 * 4 + 0][r] = v.x;
            Bs[c4 * 4 + 1][r] = v.y;
            Bs[c4 * 4 + 2][r] = v.z;
            Bs[c4 * 4 + 3][r] = v.w;
        }
        __syncthreads();

        #pragma unroll
        for (int k = 0; k < BKT; k++) {
            float a[TM];
            unsigned long long b2[TN / 2];
            #pragma unroll
            for (int i = 0; i < TM; i++)
                a[i] = As[k][ty * TM + i];
            #pragma unroll
            for (int j = 0; j < TN / 2; j++)
                b2[j] = *(const unsigned long long*)&Bs[k][tx * TN + 2 * j];
            #pragma unroll
            for (int i = 0; i < TM; i++) {
                unsigned long long a2;
                asm("mov.b64 %0, {%1, %1};"
                    : "=l"(a2) : "r"(__float_as_uint(a[i])));
                #pragma unroll
                for (int j = 0; j < TN / 2; j++)
                    asm("fma.rn.f32x2 %0, %1, %2, %0;"
                        : "+l"(acc2[i][j]) : "l"(a2), "l"(b2[j]));
            }
        }
        __syncthreads();
    }

    #pragma unroll
    for (int i = 0; i < TM; i++) {
        int m = rowBase + ty * TM + i;
        #pragma unroll
        for (int j = 0; j < TN / 2; j++) {
            int n = colBase + tx * TN + 2 * j;
            unsigned int u0 = (unsigned int)(acc2[i][j] & 0xffffffffull);
            unsigned int u1 = (unsigned int)(acc2[i][j] >> 32);
            float2 o;
            o.x = __uint_as_float(u0) + bias[n];
            o.y = __uint_as_float(u1) + bias[n + 1];
            *(float2*)(C + (size_t)m * N + n) = o;
        }
    }
}

// ---------------------------------------------------------------------------
// Persistent recurrence kernel.
// CTA c: columns n0 = (c&31)*32, rows m0 = (c>>5)*64.
// W_h slice (32 cols x 1024 k) lives in smem, TRANSPOSED to [k][n], for the
// whole kernel. Per step: stream h tile (64 x 1024) through double-buffered
// smem in natural [m][k] layout, fp32x2 FMA inner loop, sigmoid epilogue,
// grid-wide barrier.
// Thread map: tx = tid&7 (n, TN=4), ty = tid>>3 (m, TM=2). 256 threads.
// ---------------------------------------------------------------------------
__device__ __forceinline__ void grid_barrier(unsigned target)
{
    __syncthreads();
    if (threadIdx.x == 0) {
        __threadfence();
        if (atomicAdd(&g_bar[0], 1u) == GRID_P - 1) {
            atomicExch(&g_bar[0], 0u);
            __threadfence();
            atomicAdd(&g_bar[1], 1u);
        } else {
            while (((volatile unsigned*)g_bar)[1] < target) { }
        }
    }
    __syncthreads();
}

__global__ void __launch_bounds__(256, 1)
rnn_persistent(const float* __restrict__ h0,
               const float* __restrict__ W_h,
               const float* __restrict__ b_h)
{
    extern __shared__ float smem[];
    float* Ws = smem;                      // [1024][NTILE]  (k-major)
    float* As = smem + 1024 * NTILE;       // [2][BTILE][AS_STR]

    const int tid = threadIdx.x;
    const int tx  = tid & 7;               // n group: 8 x TN(4) = 32
    const int ty  = tid >> 3;              // m group: 32 x TM(2) = 64
    const int cta = blockIdx.x;
    const int n0  = (cta & 31) * NTILE;
    const int m0  = (cta >> 5) * BTILE;

    // ---- load + transpose W_h slice into smem (once) ----
    for (int i = tid; i < NTILE * 1024 / 4; i += 256) {
        int nl = i >> 8;            // 0..31
        int k4 = i & 255;           // 0..255
        float4 w = *(const float4*)(W_h + (size_t)(n0 + nl) * 1024 + k4 * 4);
        Ws[(k4 * 4 + 0) * NTILE + nl] = w.x;
        Ws[(k4 * 4 + 1) * NTILE + nl] = w.y;
        Ws[(k4 * 4 + 2) * NTILE + nl] = w.z;
        Ws[(k4 * 4 + 3) * NTILE + nl] = w.w;
    }
    const float4 bh4 = *(const float4*)(b_h + n0 + tx * 4);
    __syncthreads();

    // per-thread fixed addresses for the h-tile stage
    const int ldm  = tid >> 3;          // row within tile for LDG/STS (0..31)
    const int ldk4 = (tid & 7) * 4;     // k within tile
    float* sts0 = As + ldm * AS_STR + ldk4;
    float* sts1 = As + (ldm + 32) * AS_STR + ldk4;

    for (int t = 0; t < T_STEPS; t++) {
        const float* hin  = (t == 0) ? h0 : g_h[(t + 1) & 1];
        float*       hout = g_h[t & 1];

        // prefetch epilogue operands (DRAM latency hidden behind k-loop)
        const size_t erow = ((size_t)t * BATCH + m0 + ty * 2) * HID + n0 + tx * 4;
        float4 e0 = __ldcg((const float4*)(g_E + erow));
        float4 e1 = __ldcg((const float4*)(g_E + erow + HID));

        unsigned long long acc[2][2] = {{0ull, 0ull}, {0ull, 0ull}};

        // prefetch tile 0
        const float* gsrc = hin + (size_t)(m0 + ldm) * HID + ldk4;
        float4 r0 = __ldcg((const float4*)gsrc);
        float4 r1 = __ldcg((const float4*)(gsrc + 32 * HID));
        *(float4*)sts0 = r0;
        *(float4*)sts1 = r1;
        __syncthreads();

        #pragma unroll 1
        for (int kt = 0; kt < 1024 / BK; kt++) {
            if (kt + 1 < 1024 / BK) {
                const float* gn = gsrc + (kt + 1) * BK;
                r0 = __ldcg((const float4*)gn);
                r1 = __ldcg((const float4*)(gn + 32 * HID));
            }
            const float* Asb = As + (kt & 1) * (BTILE * AS_STR);
            const float* Wsb = Ws + kt * (BK * NTILE);

            #pragma unroll
            for (int kk = 0; kk < BK; kk += 4) {
                float4 a0 = *(const float4*)(Asb + (ty * 2 + 0) * AS_STR + kk);
                float4 a1 = *(const float4*)(Asb + (ty * 2 + 1) * AS_STR + kk);
                #pragma unroll
                for (int j = 0; j < 4; j++) {
                    const unsigned long long* bp =
                        (const unsigned long long*)(Wsb + (kk + j) * NTILE + tx * 4);
                    unsigned long long b01 = bp[0];
                    unsigned long long b23 = bp[1];
                    unsigned long long s0, s1;
                    asm("mov.b64 %0, {%1, %1};"
                        : "=l"(s0) : "r"(__float_as_uint(((const float*)&a0)[j])));
                    asm("mov.b64 %0, {%1, %1};"
                        : "=l"(s1) : "r"(__float_as_uint(((const float*)&a1)[j])));
                    asm("fma.rn.f32x2 %0, %1, %2, %0;" : "+l"(acc[0][0]) : "l"(s0), "l"(b01));
                    asm("fma.rn.f32x2 %0, %1, %2, %0;" : "+l"(acc[0][1]) : "l"(s0), "l"(b23));
                    asm("fma.rn.f32x2 %0, %1, %2, %0;" : "+l"(acc[1][0]) : "l"(s1), "l"(b01));
                    asm("fma.rn.f32x2 %0, %1, %2, %0;" : "+l"(acc[1][1]) : "l"(s1), "l"(b23));
                }
            }

            if (kt + 1 < 1024 / BK) {
                float* d0 = sts0 + ((kt + 1) & 1) * (BTILE * AS_STR);
                float* d1 = sts1 + ((kt + 1) & 1) * (BTILE * AS_STR);
                *(float4*)d0 = r0;
                *(float4*)d1 = r1;
            }
            __syncthreads();
        }

        // ---- epilogue: z = acc + b_h + E; h = sigmoid(z); store float4/row
        #pragma unroll
        for (int mi = 0; mi < 2; mi++) {
            float4 e = mi ? e1 : e0;
            unsigned int u0, u1, u2, u3;
            asm("mov.b64 {%0, %1}, %2;" : "=r"(u0), "=r"(u1) : "l"(acc[mi][0]));
            asm("mov.b64 {%0, %1}, %2;" : "=r"(u2), "=r"(u3) : "l"(acc[mi][1]));
            float4 z;
            z.x = __uint_as_float(u0) + bh4.x + e.x;
            z.y = __uint_as_float(u1) + bh4.y + e.y;
            z.z = __uint_as_float(u2) + bh4.z + e.z;
            z.w = __uint_as_float(u3) + bh4.w + e.w;
            float4 h;
            h.x = 1.0f / (1.0f + __expf(-z.x));
            h.y = 1.0f / (1.0f + __expf(-z.y));
            h.z = 1.0f / (1.0f + __expf(-z.z));
            h.w = 1.0f / (1.0f + __expf(-z.w));
            *(float4*)(hout + (size_t)(m0 + ty * 2 + mi) * HID + n0 + tx * 4) = h;
        }

        grid_barrier(t + 1);
    }
}

// ---------------------------------------------------------------------------
// Final head: logits = h @ W_o^T + b_o; out = log_softmax(logits);
// out layout: [B*OUTD] out, then [B*HID] hidden, then [B*HID] state(zeros).
// ---------------------------------------------------------------------------
__global__ void finalize_kernel(const float* __restrict__ h,
                                const float* __restrict__ W_o,
                                const float* __restrict__ b_o,
                                float* __restrict__ out)
{
    const int b   = blockIdx.x;
    const int tid = threadIdx.x;

    __shared__ float logits[OUTD];

    if (tid < 32) {
        float acc[OUTD];
        #pragma unroll
        for (int o = 0; o < OUTD; o++) acc[o] = 0.0f;
        for (int k = tid; k < HID; k += 32) {
            float hv = h[(size_t)b * HID + k];
            #pragma unroll
            for (int o = 0; o < OUTD; o++)
                acc[o] += hv * W_o[(size_t)o * HID + k];
        }
        #pragma unroll
        for (int o = 0; o < OUTD; o++) {
            float v = acc[o];
            #pragma unroll
            for (int s = 16; s > 0; s >>= 1)
                v += __shfl_xor_sync(0xffffffff, v, s);
            if (tid == 0) logits[o] = v + b_o[o];
        }
    }
    __syncthreads();

    if (tid == 0) {
        float m = logits[0];
        #pragma unroll
        for (int o = 1; o < OUTD; o++) m = fmaxf(m, logits[o]);
        float s = 0.0f;
        #pragma unroll
        for (int o = 0; o < OUTD; o++) s += expf(logits[o] - m);
        float lse = m + logf(s);
        #pragma unroll
        for (int o = 0; o < OUTD; o++)
            out[(size_t)b * OUTD + o] = logits[o] - lse;
    }

    float* hid_out = out + (size_t)BATCH * OUTD;
    float* st_out  = hid_out + (size_t)BATCH * HID;
    for (int k = tid; k < HID; k += blockDim.x) {
        hid_out[(size_t)b * HID + k] = h[(size_t)b * HID + k];
        st_out[(size_t)b * HID + k]  = 0.0f;
    }
}

extern "C" void kernel_launch(void* const* d_in, const int* in_sizes, int n_in,
                              void* d_out, int out_size)
{
    const float* x    = (const float*)d_in[0];  // [T,B,D]
    const float* h0   = (const float*)d_in[1];  // [B,H]
    const float* W_in = (const float*)d_in[3];  // [H,D]
    const float* b_in = (const float*)d_in[4];  // [H]
    const float* W_h  = (const float*)d_in[5];  // [H,H]
    const float* b_h  = (const float*)d_in[6];  // [H]
    const float* W_o  = (const float*)d_in[7];  // [O,H]
    const float* b_o  = (const float*)d_in[8];  // [O]
    float* out = (float*)d_out;

    float* Eptr = nullptr;
    float* hptr = nullptr;
    unsigned* barptr = nullptr;
    cudaGetSymbolAddress((void**)&Eptr, g_E);
    cudaGetSymbolAddress((void**)&hptr, g_h);
    cudaGetSymbolAddress((void**)&barptr, g_bar);

    // reset grid barrier state for this invocation
    cudaMemsetAsync(barptr, 0, 2 * sizeof(unsigned));

    // 1) E = x @ W_in^T + b_in : M = T*B, N = HID, K = DIM
    {
        dim3 blk(16, 16);
        dim3 grid(HID / 128, (T_STEPS * BATCH) / 128);
        gemm_nt_kernel<128, 128, 16, 8, 8><<<grid, blk>>>(
            x, W_in, b_in, Eptr, T_STEPS * BATCH, HID, DIM);
    }

    // 2) Persistent recurrence: 512 steps inside one kernel
    {
        const int smem_bytes = (1024 * NTILE + 2 * BTILE * AS_STR) * sizeof(float);
        static bool attr_set = false;
        cudaFuncSetAttribute(rnn_persistent,
                             cudaFuncAttributeMaxDynamicSharedMemorySize, smem_bytes);
        (void)attr_set;
        rnn_persistent<<<GRID_P, 256, smem_bytes>>>(h0, W_h, b_h);
    }

    // 3) Head + output tuple. Final h (t=511) lives in g_h[1].
    finalize_kernel<<<BATCH, 128>>>(hptr + (size_t)BATCH * HID, W_o, b_o, out);
}

// round 3
// speedup vs baseline: 3.3154x; 1.9049x over previous
#include <cuda_runtime.h>
#include <cuda_bf16.h>
#include <math.h>

// Problem dims (fixed by the reference)
#define T_STEPS 512
#define BATCH   256
#define DIM     1024
#define HID     1024
#define OUTD    5

// Persistent recurrence geometry: 128 CTAs = 8 m-tiles(32) x 16 n-tiles(64)
#define GRID_P  128
#define MT      32
#define NT      64

// Scratch
__device__ float          g_E[(size_t)T_STEPS * BATCH * HID];     // fp32 input proj
__device__ __nv_bfloat16  g_hbf[2][(size_t)BATCH * HID];          // bf16 h transport
__device__ float          g_hfinal[(size_t)BATCH * HID];          // fp32 final h
__device__ unsigned       g_bar[2];                               // grid barrier

// ---------------------------------------------------------------------------
// fp32x2 GEMM for the input projection (proven in R1/R2): C = A @ W^T + bias
// ---------------------------------------------------------------------------
template<int BM, int BN, int BKT, int TM, int TN>
__global__ void gemm_nt_kernel(const float* __restrict__ A,
                               const float* __restrict__ W,
                               const float* __restrict__ bias,
                               float* __restrict__ C,
                               int M, int N, int K)
{
    __shared__ __align__(16) float As[BKT][BM + 2];
    __shared__ __align__(16) float Bs[BKT][BN + 2];

    const int tx  = threadIdx.x;
    const int ty  = threadIdx.y;
    const int tid = ty * 16 + tx;

    const int rowBase = blockIdx.y * BM;
    const int colBase = blockIdx.x * BN;

    unsigned long long acc2[TM][TN / 2];
    #pragma unroll
    for (int i = 0; i < TM; i++)
        #pragma unroll
        for (int j = 0; j < TN / 2; j++)
            acc2[i][j] = 0ull;

    constexpr int AK4 = BKT / 4;

    for (int k0 = 0; k0 < K; k0 += BKT) {
        for (int i = tid; i < (BM * BKT) / 4; i += 256) {
            int r  = i / AK4;
            int c4 = i % AK4;
            float4 v = *(const float4*)(A + (size_t)(rowBase + r) * K + k0 + c4 * 4);
            As[c4 * 4 + 0][r] = v.x;
            As[c4 * 4 + 1][r] = v.y;
            As[c4 * 4 + 2][r] = v.z;
            As[c4 * 4 + 3][r] = v.w;
        }
        for (int i = tid; i < (BN * BKT) / 4; i += 256) {
            int r  = i / AK4;
            int c4 = i % AK4;
            float4 v = *(const float4*)(W + (size_t)(colBase + r) * K + k0 + c4 * 4);
            Bs[c4 * 4 + 0][r] = v.x;
            Bs[c4 * 4 + 1][r] = v.y;
            Bs[c4 * 4 + 2][r] = v.z;
            Bs[c4 * 4 + 3][r] = v.w;
        }
        __syncthreads();

        #pragma unroll
        for (int k = 0; k < BKT; k++) {
            float a[TM];
            unsigned long long b2[TN / 2];
            #pragma unroll
            for (int i = 0; i < TM; i++)
                a[i] = As[k][ty * TM + i];
            #pragma unroll
            for (int j = 0; j < TN / 2; j++)
                b2[j] = *(const unsigned long long*)&Bs[k][tx * TN + 2 * j];
            #pragma unroll
            for (int i = 0; i < TM; i++) {
                unsigned long long a2;
                asm("mov.b64 %0, {%1, %1};"
                    : "=l"(a2) : "r"(__float_as_uint(a[i])));
                #pragma unroll
                for (int j = 0; j < TN / 2; j++)
                    asm("fma.rn.f32x2 %0, %1, %2, %0;"
                        : "+l"(acc2[i][j]) : "l"(a2), "l"(b2[j]));
            }
        }
        __syncthreads();
    }

    #pragma unroll
    for (int i = 0; i < TM; i++) {
        int m = rowBase + ty * TM + i;
        #pragma unroll
        for (int j = 0; j < TN / 2; j++) {
            int n = colBase + tx * TN + 2 * j;
            unsigned int u0 = (unsigned int)(acc2[i][j] & 0xffffffffull);
            unsigned int u1 = (unsigned int)(acc2[i][j] >> 32);
            float2 o;
            o.x = __uint_as_float(u0) + bias[n];
            o.y = __uint_as_float(u1) + bias[n + 1];
            *(float2*)(C + (size_t)m * N + n) = o;
        }
    }
}

// ---------------------------------------------------------------------------
// h0 -> bf16 transport buffer (read at t=0 as g_hbf[1])
// ---------------------------------------------------------------------------
__global__ void h0_to_bf16(const float* __restrict__ h0)
{
    int i = blockIdx.x * 256 + threadIdx.x;
    g_hbf[1][i] = __float2bfloat16(h0[i]);
}

// ---------------------------------------------------------------------------
// bf16 mma.sync helper (m16n8k16, fp32 accumulate)
// ---------------------------------------------------------------------------
__device__ __forceinline__ void mma_bf16(float d[4],
                                         unsigned a0, unsigned a1,
                                         unsigned a2, unsigned a3,
                                         unsigned b0, unsigned b1)
{
    asm volatile(
        "mma.sync.aligned.m16n8k16.row.col.f32.bf16.bf16.f32 "
        "{%0,%1,%2,%3}, {%4,%5,%6,%7}, {%8,%9}, {%0,%1,%2,%3};"
        : "+f"(d[0]), "+f"(d[1]), "+f"(d[2]), "+f"(d[3])
        : "r"(a0), "r"(a1), "r"(a2), "r"(a3), "r"(b0), "r"(b1));
}

__device__ __forceinline__ float sigmoidf_fast(float x)
{
    return 1.0f / (1.0f + __expf(-x));
}

// ---------------------------------------------------------------------------
// Grid barrier (R2-proven structure + per-thread fence)
// ---------------------------------------------------------------------------
__device__ __forceinline__ void grid_barrier(unsigned target)
{
    __threadfence();
    __syncthreads();
    if (threadIdx.x == 0) {
        if (atomicAdd(&g_bar[0], 1u) == GRID_P - 1) {
            atomicExch(&g_bar[0], 0u);
            __threadfence();
            atomicAdd(&g_bar[1], 1u);
        } else {
            while (((volatile unsigned*)g_bar)[1] < target) { }
        }
    }
    __syncthreads();
}

// ---------------------------------------------------------------------------
// Persistent recurrence with bf16 tensor-core mma.
// CTA: m0 = (cta>>4)*32, n0 = (cta&15)*64. 8 warps, warp tile 16m x 16n.
// Ws (smem, 128KB): W_h slice in fragment-shuffled bf16 layout:
//   word(s, n, p) = s*512 + n*8 + (p&3)*2 + (p>>2),  p = (k%16)/2
// As (smem, 2 x 8KB): h chunk (32m x 128k bf16), same k-pairing, plus an XOR
//   swizzle of the word-pair index by (slice&3) to kill STS bank conflicts.
// ---------------------------------------------------------------------------
__global__ void __launch_bounds__(256, 1)
rnn_persistent(const float* __restrict__ W_h,
               const float* __restrict__ b_h)
{
    extern __shared__ unsigned smw[];
    unsigned* Ws = smw;              // 32768 words (128KB)
    unsigned* As = smw + 32768;      // 4096 words (2 x 8KB)

    const int tid  = threadIdx.x;
    const int lane = tid & 31;
    const int w    = tid >> 5;
    const int qid  = lane >> 2;      // 0..7
    const int c    = lane & 3;       // 0..3
    const int mw   = (w >> 2) * 16;  // warp m offset in CTA tile
    const int nw   = (w & 3) * 16;   // warp n offset
    const int cta  = blockIdx.x;
    const int m0   = (cta >> 4) * MT;
    const int n0   = (cta & 15) * NT;

    // ---- fill Ws (once): fp32 -> bf16x2, fragment-shuffled ----
    for (int i = tid; i < NT * 512; i += 256) {
        int n  = i >> 9;
        int kp = i & 511;
        int k  = kp * 2;
        int s  = k >> 4;
        int p  = (k & 15) >> 1;
        float2 wv = *(const float2*)(W_h + (size_t)(n0 + n) * HID + k);
        __nv_bfloat162 bb = __float22bfloat162_rn(wv);
        Ws[s * 512 + n * 8 + (p & 3) * 2 + (p >> 2)] = *(unsigned*)&bb;
    }
    const float2 bh0 = *(const float2*)(b_h + n0 + nw + 2 * c);
    const float2 bh1 = *(const float2*)(b_h + n0 + nw + 8 + 2 * c);
    __syncthreads();

    // staging thread map: row = tid>>3 (0..31), slice-in-chunk = tid&7
    const int srow = tid >> 3;
    const int ssl  = tid & 7;
    const int sx   = ssl & 3;

    for (int t = 0; t < T_STEPS; t++) {
        const __nv_bfloat16* hin  = g_hbf[(t + 1) & 1];
        __nv_bfloat16*       hout = g_hbf[t & 1];

        // prefetch epilogue E operands (c-fragment addressing)
        const float* eb = g_E + ((size_t)t * BATCH + m0 + mw + qid) * HID
                              + n0 + nw + 2 * c;
        float2 e00 = __ldg((const float2*)eb);
        float2 e01 = __ldg((const float2*)(eb + 8));
        float2 e10 = __ldg((const float2*)(eb + 8 * HID));
        float2 e11 = __ldg((const float2*)(eb + 8 * HID + 8));

        float d0[4] = {0.f, 0.f, 0.f, 0.f};
        float d1[4] = {0.f, 0.f, 0.f, 0.f};

        // stage chunk 0
        const __nv_bfloat16* gsrc = hin + (size_t)(m0 + srow) * HID + ssl * 16;
        int4 v0 = __ldcg((const int4*)gsrc);
        int4 v1 = __ldcg((const int4*)(gsrc + 8));
        {
            uint2* dp = (uint2*)(As + ssl * 256 + srow * 8);
            dp[0 ^ sx] = make_uint2(v0.x, v1.x);
            dp[1 ^ sx] = make_uint2(v0.y, v1.y);
            dp[2 ^ sx] = make_uint2(v0.z, v1.z);
            dp[3 ^ sx] = make_uint2(v0.w, v1.w);
        }
        __syncthreads();

        #pragma unroll 1
        for (int ch = 0; ch < 8; ch++) {
            if (ch < 7) {
                const __nv_bfloat16* gn = gsrc + (ch + 1) * 128;
                v0 = __ldcg((const int4*)gn);
                v1 = __ldcg((const int4*)(gn + 8));
            }
            const unsigned* Ab = As + (ch & 1) * 2048;
            #pragma unroll
            for (int sl = 0; sl < 8; sl++) {
                int aoff = sl * 256 + (mw + qid) * 8 + 2 * (c ^ (sl & 3));
                uint2 aLo = *(const uint2*)(Ab + aoff);        // {a0, a2}
                uint2 aHi = *(const uint2*)(Ab + aoff + 64);   // {a1, a3}
                const unsigned* Wb = Ws + (ch * 8 + sl) * 512 + (nw + qid) * 8 + 2 * c;
                uint2 b0 = *(const uint2*)(Wb);                // {b0, b1} g=0
                uint2 b1 = *(const uint2*)(Wb + 64);           // g=1
                mma_bf16(d0, aLo.x, aHi.x, aLo.y, aHi.y, b0.x, b0.y);
                mma_bf16(d1, aLo.x, aHi.x, aLo.y, aHi.y, b1.x, b1.y);
            }
            if (ch < 7) {
                uint2* dp = (uint2*)(As + ((ch + 1) & 1) * 2048 + ssl * 256 + srow * 8);
                dp[0 ^ sx] = make_uint2(v0.x, v1.x);
                dp[1 ^ sx] = make_uint2(v0.y, v1.y);
                dp[2 ^ sx] = make_uint2(v0.z, v1.z);
                dp[3 ^ sx] = make_uint2(v0.w, v1.w);
            }
            __syncthreads();
        }

        // ---- epilogue: z = d + b_h + E; h = sigmoid(z) (all fp32) ----
        float s00x = sigmoidf_fast(d0[0] + bh0.x + e00.x);
        float s00y = sigmoidf_fast(d0[1] + bh0.y + e00.y);
        float s10x = sigmoidf_fast(d0[2] + bh0.x + e10.x);
        float s10y = sigmoidf_fast(d0[3] + bh0.y + e10.y);
        float s01x = sigmoidf_fast(d1[0] + bh1.x + e01.x);
        float s01y = sigmoidf_fast(d1[1] + bh1.y + e01.y);
        float s11x = sigmoidf_fast(d1[2] + bh1.x + e11.x);
        float s11y = sigmoidf_fast(d1[3] + bh1.y + e11.y);

        __nv_bfloat16* ho = hout + (size_t)(m0 + mw + qid) * HID + n0 + nw + 2 * c;
        *(__nv_bfloat162*)(ho)               = __float22bfloat162_rn(make_float2(s00x, s00y));
        *(__nv_bfloat162*)(ho + 8)           = __float22bfloat162_rn(make_float2(s01x, s01y));
        *(__nv_bfloat162*)(ho + 8 * HID)     = __float22bfloat162_rn(make_float2(s10x, s10y));
        *(__nv_bfloat162*)(ho + 8 * HID + 8) = __float22bfloat162_rn(make_float2(s11x, s11y));

        if (t == T_STEPS - 1) {
            float* hf = g_hfinal + (size_t)(m0 + mw + qid) * HID + n0 + nw + 2 * c;
            *(float2*)(hf)               = make_float2(s00x, s00y);
            *(float2*)(hf + 8)           = make_float2(s01x, s01y);
            *(float2*)(hf + 8 * HID)     = make_float2(s10x, s10y);
            *(float2*)(hf + 8 * HID + 8) = make_float2(s11x, s11y);
        }

        grid_barrier(t + 1);
    }
}

// ---------------------------------------------------------------------------
// Final head: logits = h @ W_o^T + b_o; out = log_softmax(logits);
// out layout: [B*OUTD] out, [B*HID] hidden (fp32 final h), [B*HID] state copy.
// ---------------------------------------------------------------------------
__global__ void finalize_kernel(const float* __restrict__ h,
                                const float* __restrict__ state_in,
                                const float* __restrict__ W_o,
                                const float* __restrict__ b_o,
                                float* __restrict__ out)
{
    const int b   = blockIdx.x;
    const int tid = threadIdx.x;

    __shared__ float logits[OUTD];

    if (tid < 32) {
        float acc[OUTD];
        #pragma unroll
        for (int o = 0; o < OUTD; o++) acc[o] = 0.0f;
        for (int k = tid; k < HID; k += 32) {
            float hv = h[(size_t)b * HID + k];
            #pragma unroll
            for (int o = 0; o < OUTD; o++)
                acc[o] += hv * W_o[(size_t)o * HID + k];
        }
        #pragma unroll
        for (int o = 0; o < OUTD; o++) {
            float v = acc[o];
            #pragma unroll
            for (int s = 16; s > 0; s >>= 1)
                v += __shfl_xor_sync(0xffffffff, v, s);
            if (tid == 0) logits[o] = v + b_o[o];
        }
    }
    __syncthreads();

    if (tid == 0) {
        float m = logits[0];
        #pragma unroll
        for (int o = 1; o < OUTD; o++) m = fmaxf(m, logits[o]);
        float s = 0.0f;
        #pragma unroll
        for (int o = 0; o < OUTD; o++) s += expf(logits[o] - m);
        float lse = m + logf(s);
        #pragma unroll
        for (int o = 0; o < OUTD; o++)
            out[(size_t)b * OUTD + o] = logits[o] - lse;
    }

    float* hid_out = out + (size_t)BATCH * OUTD;
    float* st_out  = hid_out + (size_t)BATCH * HID;
    for (int k = tid; k < HID; k += blockDim.x) {
        hid_out[(size_t)b * HID + k] = h[(size_t)b * HID + k];
        st_out[(size_t)b * HID + k]  = state_in[(size_t)b * HID + k];
    }
}

extern "C" void kernel_launch(void* const* d_in, const int* in_sizes, int n_in,
                              void* d_out, int out_size)
{
    const float* x    = (const float*)d_in[0];  // [T,B,D]
    const float* h0   = (const float*)d_in[1];  // [B,H]
    const float* st   = (const float*)d_in[2];  // [B,H]
    const float* W_in = (const float*)d_in[3];  // [H,D]
    const float* b_in = (const float*)d_in[4];  // [H]
    const float* W_h  = (const float*)d_in[5];  // [H,H]
    const float* b_h  = (const float*)d_in[6];  // [H]
    const float* W_o  = (const float*)d_in[7];  // [O,H]
    const float* b_o  = (const float*)d_in[8];  // [O]
    float* out = (float*)d_out;

    float* Eptr = nullptr;
    float* hfin = nullptr;
    unsigned* barptr = nullptr;
    cudaGetSymbolAddress((void**)&Eptr, g_E);
    cudaGetSymbolAddress((void**)&hfin, g_hfinal);
    cudaGetSymbolAddress((void**)&barptr, g_bar);

    cudaMemsetAsync(barptr, 0, 2 * sizeof(unsigned));

    // 0) h0 -> bf16 transport buffer (parity slot read at t=0)
    h0_to_bf16<<<(BATCH * HID) / 256, 256>>>(h0);

    // 1) E = x @ W_in^T + b_in (fp32)
    {
        dim3 blk(16, 16);
        dim3 grid(HID / 128, (T_STEPS * BATCH) / 128);
        gemm_nt_kernel<128, 128, 16, 8, 8><<<grid, blk>>>(
            x, W_in, b_in, Eptr, T_STEPS * BATCH, HID, DIM);
    }

    // 2) Persistent recurrence (bf16 tensor cores, fp32 accumulate)
    {
        const int smem_bytes = (32768 + 4096) * sizeof(unsigned);  // 147456
        cudaFuncSetAttribute(rnn_persistent,
                             cudaFuncAttributeMaxDynamicSharedMemorySize, smem_bytes);
        rnn_persistent<<<GRID_P, 256, smem_bytes>>>(W_h, b_h);
    }

    // 3) Head + output tuple
    finalize_kernel<<<BATCH, 128>>>(hfin, st, W_o, b_o, out);
}

// round 4
// speedup vs baseline: 5.1770x; 1.5615x over previous
#include <cuda_runtime.h>
#include <cuda_bf16.h>
#include <math.h>

// Problem dims (fixed by the reference)
#define T_STEPS 512
#define BATCH   256
#define DIM     1024
#define HID     1024
#define OUTD    5

// Persistent recurrence geometry: 128 CTAs = 8 m-tiles(32) x 16 n-tiles(64)
#define GRID_P  128
#define MT      32
#define NT      64

// Scratch
__device__ float          g_E[(size_t)T_STEPS * BATCH * HID];     // fp32 input proj
__device__ __nv_bfloat16  g_hbf[2][(size_t)BATCH * HID];          // bf16 h transport
__device__ float          g_hfinal[(size_t)BATCH * HID];          // fp32 final h
__device__ unsigned       g_grp[8][32];                           // per-m-group barrier ctrs

// ---------------------------------------------------------------------------
// bf16 mma.sync helper (m16n8k16, fp32 accumulate)
// ---------------------------------------------------------------------------
__device__ __forceinline__ void mma_bf16(float d[4],
                                         unsigned a0, unsigned a1,
                                         unsigned a2, unsigned a3,
                                         unsigned b0, unsigned b1)
{
    asm volatile(
        "mma.sync.aligned.m16n8k16.row.col.f32.bf16.bf16.f32 "
        "{%0,%1,%2,%3}, {%4,%5,%6,%7}, {%8,%9}, {%0,%1,%2,%3};"
        : "+f"(d[0]), "+f"(d[1]), "+f"(d[2]), "+f"(d[3])
        : "r"(a0), "r"(a1), "r"(a2), "r"(a3), "r"(b0), "r"(b1));
}

__device__ __forceinline__ float sigmoidf_fast(float x)
{
    return 1.0f / (1.0f + __expf(-x));
}

// split a float pair into bf16 hi + bf16 lo (residual) packed words
__device__ __forceinline__ void split2(float a, float b, unsigned& hi, unsigned& lo)
{
    __nv_bfloat162 h = __float22bfloat162_rn(make_float2(a, b));
    float ra = a - __low2float(h);
    float rb = b - __high2float(h);
    __nv_bfloat162 l = __float22bfloat162_rn(make_float2(ra, rb));
    hi = *(unsigned*)&h;
    lo = *(unsigned*)&l;
}

// ---------------------------------------------------------------------------
// E = x @ W_in^T + b_in via error-compensated bf16 tensor-core GEMM.
// E = x_hi*W_hi + x_hi*W_lo + x_lo*W_hi  (fp32 accumulate, err ~ 1e-5)
// CTA tile 128m x 64n, K chunked by 128. 256 threads, 8 warps (warp = 16 m).
// smem 96KB, 2 CTAs/SM. Fragment layout identical to the validated
// rnn_persistent layout:
//   word(slice, row, p) = slice*256(or 512) + row*8 + (p&3)*2 + (p>>2),
//   with uint2-index XOR swizzle by (slice&3) on both store and load.
// ---------------------------------------------------------------------------
__global__ void __launch_bounds__(256, 2)
egemm_bf16x3(const float* __restrict__ X,     // [131072, 1024]
             const float* __restrict__ Wg,    // [1024, 1024]
             const float* __restrict__ bias,  // [1024]
             float* __restrict__ E)
{
    extern __shared__ unsigned es[];
    unsigned* Ahi = es;             // 4 groups x 2048 words = 8192 (32KB)
    unsigned* Alo = es + 8192;      // 8192
    unsigned* Bhi = es + 16384;     // 8 slices x 512 words = 4096 (16KB)
    unsigned* Blo = es + 20480;     // 4096

    const int tid  = threadIdx.x;
    const int lane = tid & 31;
    const int w    = tid >> 5;
    const int qid  = lane >> 2;
    const int c    = lane & 3;
    const int g    = w >> 1;             // A row-group for this warp
    const int subm = (w & 1) * 16;       // row offset within group

    const int n0 = blockIdx.x * 64;
    const int m0 = blockIdx.y * 128;

    const int srow = tid >> 3;           // 0..31
    const int ssl  = tid & 7;            // slice 0..7
    const int sx   = ssl & 3;

    float acc[4][2][4];
    #pragma unroll
    for (int a = 0; a < 4; a++)
        #pragma unroll
        for (int b = 0; b < 2; b++)
            #pragma unroll
            for (int d = 0; d < 4; d++) acc[a][b][d] = 0.0f;

    for (int ch = 0; ch < 8; ch++) {
        __syncthreads();
        // ---- stage A: 128 rows x 128 k (4 row-slices per thread) ----
        const float* xbase = X + (size_t)(m0 + srow) * 1024 + ch * 128 + ssl * 16;
        #pragma unroll
        for (int jj = 0; jj < 4; jj++) {
            const float4* p = (const float4*)(xbase + (size_t)jj * 32 * 1024);
            float4 f0 = p[0], f1 = p[1], f2 = p[2], f3 = p[3];
            unsigned h[8], l[8];
            split2(f0.x, f0.y, h[0], l[0]); split2(f0.z, f0.w, h[1], l[1]);
            split2(f1.x, f1.y, h[2], l[2]); split2(f1.z, f1.w, h[3], l[3]);
            split2(f2.x, f2.y, h[4], l[4]); split2(f2.z, f2.w, h[5], l[5]);
            split2(f3.x, f3.y, h[6], l[6]); split2(f3.z, f3.w, h[7], l[7]);
            uint2* dh = (uint2*)&Ahi[jj * 2048 + ssl * 256 + srow * 8];
            uint2* dl = (uint2*)&Alo[jj * 2048 + ssl * 256 + srow * 8];
            dh[0 ^ sx] = make_uint2(h[0], h[4]); dh[1 ^ sx] = make_uint2(h[1], h[5]);
            dh[2 ^ sx] = make_uint2(h[2], h[6]); dh[3 ^ sx] = make_uint2(h[3], h[7]);
            dl[0 ^ sx] = make_uint2(l[0], l[4]); dl[1 ^ sx] = make_uint2(l[1], l[5]);
            dl[2 ^ sx] = make_uint2(l[2], l[6]); dl[3 ^ sx] = make_uint2(l[3], l[7]);
        }
        // ---- stage B: 64 n-rows x 128 k (2 row-slices per thread) ----
        #pragma unroll
        for (int jj = 0; jj < 2; jj++) {
            int nrow = srow + jj * 32;
            const float4* p = (const float4*)(Wg + (size_t)(n0 + nrow) * 1024
                                              + ch * 128 + ssl * 16);
            float4 f0 = p[0], f1 = p[1], f2 = p[2], f3 = p[3];
            unsigned h[8], l[8];
            split2(f0.x, f0.y, h[0], l[0]); split2(f0.z, f0.w, h[1], l[1]);
            split2(f1.x, f1.y, h[2], l[2]); split2(f1.z, f1.w, h[3], l[3]);
            split2(f2.x, f2.y, h[4], l[4]); split2(f2.z, f2.w, h[5], l[5]);
            split2(f3.x, f3.y, h[6], l[6]); split2(f3.z, f3.w, h[7], l[7]);
            uint2* dh = (uint2*)&Bhi[ssl * 512 + nrow * 8];
            uint2* dl = (uint2*)&Blo[ssl * 512 + nrow * 8];
            dh[0 ^ sx] = make_uint2(h[0], h[4]); dh[1 ^ sx] = make_uint2(h[1], h[5]);
            dh[2 ^ sx] = make_uint2(h[2], h[6]); dh[3 ^ sx] = make_uint2(h[3], h[7]);
            dl[0 ^ sx] = make_uint2(l[0], l[4]); dl[1 ^ sx] = make_uint2(l[1], l[5]);
            dl[2 ^ sx] = make_uint2(l[2], l[6]); dl[3 ^ sx] = make_uint2(l[3], l[7]);
        }
        __syncthreads();

        // ---- mma: 8 slices x 4 n16-groups x 2 halves x 3 terms ----
        #pragma unroll
        for (int sl = 0; sl < 8; sl++) {
            int axw = g * 2048 + sl * 256 + (subm + qid) * 8 + 2 * (c ^ (sl & 3));
            uint2 ah0 = *(const uint2*)&Ahi[axw];
            uint2 ah1 = *(const uint2*)&Ahi[axw + 64];
            uint2 al0 = *(const uint2*)&Alo[axw];
            uint2 al1 = *(const uint2*)&Alo[axw + 64];
            #pragma unroll
            for (int ng = 0; ng < 4; ng++) {
                int bxw = sl * 512 + ng * 128 + qid * 8 + 2 * (c ^ (sl & 3));
                uint2 bh0 = *(const uint2*)&Bhi[bxw];
                uint2 bh1 = *(const uint2*)&Bhi[bxw + 64];
                uint2 bl0 = *(const uint2*)&Blo[bxw];
                uint2 bl1 = *(const uint2*)&Blo[bxw + 64];
                mma_bf16(acc[ng][0], ah0.x, ah1.x, ah0.y, ah1.y, bh0.x, bh0.y);
                mma_bf16(acc[ng][0], ah0.x, ah1.x, ah0.y, ah1.y, bl0.x, bl0.y);
                mma_bf16(acc[ng][0], al0.x, al1.x, al0.y, al1.y, bh0.x, bh0.y);
                mma_bf16(acc[ng][1], ah0.x, ah1.x, ah0.y, ah1.y, bh1.x, bh1.y);
                mma_bf16(acc[ng][1], ah0.x, ah1.x, ah0.y, ah1.y, bl1.x, bl1.y);
                mma_bf16(acc[ng][1], al0.x, al1.x, al0.y, al1.y, bh1.x, bh1.y);
            }
        }
    }

    // ---- epilogue: add bias, store fp32 E ----
    const int mrow = m0 + w * 16 + qid;
    #pragma unroll
    for (int ng = 0; ng < 4; ng++) {
        #pragma unroll
        for (int hh = 0; hh < 2; hh++) {
            int col = n0 + ng * 16 + hh * 8 + 2 * c;
            float2 b2 = *(const float2*)(bias + col);
            float2 o0, o1;
            o0.x = acc[ng][hh][0] + b2.x; o0.y = acc[ng][hh][1] + b2.y;
            o1.x = acc[ng][hh][2] + b2.x; o1.y = acc[ng][hh][3] + b2.y;
            *(float2*)&E[(size_t)mrow * 1024 + col]       = o0;
            *(float2*)&E[(size_t)(mrow + 8) * 1024 + col] = o1;
        }
    }
}

// ---------------------------------------------------------------------------
// h0 -> bf16 transport buffer (read at t=0 as g_hbf[1])
// ---------------------------------------------------------------------------
__global__ void h0_to_bf16(const float* __restrict__ h0)
{
    int i = blockIdx.x * 256 + threadIdx.x;
    g_hbf[1][i] = __float2bfloat16(h0[i]);
}

// ---------------------------------------------------------------------------
// Per-m-group barrier: 16 CTAs, release/acquire atomics, monotonic counter.
// No __threadfence (no MEMBAR.GPU / CCTL.IVALL storm), no shared-line polling.
// ---------------------------------------------------------------------------
__device__ __forceinline__ void group_barrier(int grp, unsigned target)
{
    __syncthreads();
    if (threadIdx.x == 0) {
        unsigned* ctr = &g_grp[grp][0];
        asm volatile("red.release.gpu.global.add.u32 [%0], %1;"
                     :: "l"(ctr), "r"(1u) : "memory");
        unsigned v;
        do {
            asm volatile("ld.acquire.gpu.global.u32 %0, [%1];"
                         : "=r"(v) : "l"(ctr) : "memory");
        } while (v < target);
    }
    __syncthreads();
}

// ---------------------------------------------------------------------------
// Persistent recurrence with bf16 tensor-core mma (layout validated in R2).
// CTA: m0 = (cta>>4)*32, n0 = (cta&15)*64. 8 warps, warp tile 16m x 16n.
// Sync: only within the 16-CTA group sharing this CTA's m-block.
// ---------------------------------------------------------------------------
__global__ void __launch_bounds__(256, 1)
rnn_persistent(const float* __restrict__ W_h,
               const float* __restrict__ b_h)
{
    extern __shared__ unsigned smw[];
    unsigned* Ws = smw;              // 32768 words (128KB)
    unsigned* As = smw + 32768;      // 4096 words (2 x 8KB)

    const int tid  = threadIdx.x;
    const int lane = tid & 31;
    const int w    = tid >> 5;
    const int qid  = lane >> 2;
    const int c    = lane & 3;
    const int mw   = (w >> 2) * 16;
    const int nw   = (w & 3) * 16;
    const int cta  = blockIdx.x;
    const int grp  = cta >> 4;
    const int m0   = grp * MT;
    const int n0   = (cta & 15) * NT;

    // ---- fill Ws (once): fp32 -> bf16x2, fragment-shuffled ----
    for (int i = tid; i < NT * 512; i += 256) {
        int n  = i >> 9;
        int kp = i & 511;
        int k  = kp * 2;
        int s  = k >> 4;
        int p  = (k & 15) >> 1;
        float2 wv = *(const float2*)(W_h + (size_t)(n0 + n) * HID + k);
        __nv_bfloat162 bb = __float22bfloat162_rn(wv);
        Ws[s * 512 + n * 8 + (p & 3) * 2 + (p >> 2)] = *(unsigned*)&bb;
    }
    const float2 bh0 = *(const float2*)(b_h + n0 + nw + 2 * c);
    const float2 bh1 = *(const float2*)(b_h + n0 + nw + 8 + 2 * c);
    __syncthreads();

    const int srow = tid >> 3;
    const int ssl  = tid & 7;
    const int sx   = ssl & 3;

    for (int t = 0; t < T_STEPS; t++) {
        const __nv_bfloat16* hin  = g_hbf[(t + 1) & 1];
        __nv_bfloat16*       hout = g_hbf[t & 1];

        const float* eb = g_E + ((size_t)t * BATCH + m0 + mw + qid) * HID
                              + n0 + nw + 2 * c;
        float2 e00 = __ldg((const float2*)eb);
        float2 e01 = __ldg((const float2*)(eb + 8));
        float2 e10 = __ldg((const float2*)(eb + 8 * HID));
        float2 e11 = __ldg((const float2*)(eb + 8 * HID + 8));

        float d0[4] = {0.f, 0.f, 0.f, 0.f};
        float d1[4] = {0.f, 0.f, 0.f, 0.f};

        const __nv_bfloat16* gsrc = hin + (size_t)(m0 + srow) * HID + ssl * 16;
        int4 v0 = __ldcg((const int4*)gsrc);
        int4 v1 = __ldcg((const int4*)(gsrc + 8));
        {
            uint2* dp = (uint2*)(As + ssl * 256 + srow * 8);
            dp[0 ^ sx] = make_uint2(v0.x, v1.x);
            dp[1 ^ sx] = make_uint2(v0.y, v1.y);
            dp[2 ^ sx] = make_uint2(v0.z, v1.z);
            dp[3 ^ sx] = make_uint2(v0.w, v1.w);
        }
        __syncthreads();

        #pragma unroll 1
        for (int ch = 0; ch < 8; ch++) {
            if (ch < 7) {
                const __nv_bfloat16* gn = gsrc + (ch + 1) * 128;
                v0 = __ldcg((const int4*)gn);
                v1 = __ldcg((const int4*)(gn + 8));
            }
            const unsigned* Ab = As + (ch & 1) * 2048;
            #pragma unroll
            for (int sl = 0; sl < 8; sl++) {
                int aoff = sl * 256 + (mw + qid) * 8 + 2 * (c ^ (sl & 3));
                uint2 aLo = *(const uint2*)(Ab + aoff);
                uint2 aHi = *(const uint2*)(Ab + aoff + 64);
                const unsigned* Wb = Ws + (ch * 8 + sl) * 512 + (nw + qid) * 8 + 2 * c;
                uint2 b0 = *(const uint2*)(Wb);
                uint2 b1 = *(const uint2*)(Wb + 64);
                mma_bf16(d0, aLo.x, aHi.x, aLo.y, aHi.y, b0.x, b0.y);
                mma_bf16(d1, aLo.x, aHi.x, aLo.y, aHi.y, b1.x, b1.y);
            }
            if (ch < 7) {
                uint2* dp = (uint2*)(As + ((ch + 1) & 1) * 2048 + ssl * 256 + srow * 8);
                dp[0 ^ sx] = make_uint2(v0.x, v1.x);
                dp[1 ^ sx] = make_uint2(v0.y, v1.y);
                dp[2 ^ sx] = make_uint2(v0.z, v1.z);
                dp[3 ^ sx] = make_uint2(v0.w, v1.w);
            }
            __syncthreads();
        }

        // ---- epilogue: z = d + b_h + E; h = sigmoid(z) (all fp32) ----
        float s00x = sigmoidf_fast(d0[0] + bh0.x + e00.x);
        float s00y = sigmoidf_fast(d0[1] + bh0.y + e00.y);
        float s10x = sigmoidf_fast(d0[2] + bh0.x + e10.x);
        float s10y = sigmoidf_fast(d0[3] + bh0.y + e10.y);
        float s01x = sigmoidf_fast(d1[0] + bh1.x + e01.x);
        float s01y = sigmoidf_fast(d1[1] + bh1.y + e01.y);
        float s11x = sigmoidf_fast(d1[2] + bh1.x + e11.x);
        float s11y = sigmoidf_fast(d1[3] + bh1.y + e11.y);

        __nv_bfloat16* ho = hout + (size_t)(m0 + mw + qid) * HID + n0 + nw + 2 * c;
        *(__nv_bfloat162*)(ho)               = __float22bfloat162_rn(make_float2(s00x, s00y));
        *(__nv_bfloat162*)(ho + 8)           = __float22bfloat162_rn(make_float2(s01x, s01y));
        *(__nv_bfloat162*)(ho + 8 * HID)     = __float22bfloat162_rn(make_float2(s10x, s10y));
        *(__nv_bfloat162*)(ho + 8 * HID + 8) = __float22bfloat162_rn(make_float2(s11x, s11y));

        if (t == T_STEPS - 1) {
            float* hf = g_hfinal + (size_t)(m0 + mw + qid) * HID + n0 + nw + 2 * c;
            *(float2*)(hf)               = make_float2(s00x, s00y);
            *(float2*)(hf + 8)           = make_float2(s01x, s01y);
            *(float2*)(hf + 8 * HID)     = make_float2(s10x, s10y);
            *(float2*)(hf + 8 * HID + 8) = make_float2(s11x, s11y);
        } else {
            group_barrier(grp, 16u * (t + 1));
        }
    }
}

// ---------------------------------------------------------------------------
// Final head: logits = h @ W_o^T + b_o; out = log_softmax(logits);
// out layout: [B*OUTD] out, [B*HID] hidden (fp32 final h), [B*HID] state copy.
// ---------------------------------------------------------------------------
__global__ void finalize_kernel(const float* __restrict__ h,
                                const float* __restrict__ state_in,
                                const float* __restrict__ W_o,
                                const float* __restrict__ b_o,
                                float* __restrict__ out)
{
    const int b   = blockIdx.x;
    const int tid = threadIdx.x;

    __shared__ float logits[OUTD];

    if (tid < 32) {
        float acc[OUTD];
        #pragma unroll
        for (int o = 0; o < OUTD; o++) acc[o] = 0.0f;
        for (int k = tid; k < HID; k += 32) {
            float hv = h[(size_t)b * HID + k];
            #pragma unroll
            for (int o = 0; o < OUTD; o++)
                acc[o] += hv * W_o[(size_t)o * HID + k];
        }
        #pragma unroll
        for (int o = 0; o < OUTD; o++) {
            float v = acc[o];
            #pragma unroll
            for (int s = 16; s > 0; s >>= 1)
                v += __shfl_xor_sync(0xffffffff, v, s);
            if (tid == 0) logits[o] = v + b_o[o];
        }
    }
    __syncthreads();

    if (tid == 0) {
        float m = logits[0];
        #pragma unroll
        for (int o = 1; o < OUTD; o++) m = fmaxf(m, logits[o]);
        float s = 0.0f;
        #pragma unroll
        for (int o = 0; o < OUTD; o++) s += expf(logits[o] - m);
        float lse = m + logf(s);
        #pragma unroll
        for (int o = 0; o < OUTD; o++)
            out[(size_t)b * OUTD + o] = logits[o] - lse;
    }

    float* hid_out = out + (size_t)BATCH * OUTD;
    float* st_out  = hid_out + (size_t)BATCH * HID;
    for (int k = tid; k < HID; k += blockDim.x) {
        hid_out[(size_t)b * HID + k] = h[(size_t)b * HID + k];
        st_out[(size_t)b * HID + k]  = state_in[(size_t)b * HID + k];
    }
}

extern "C" void kernel_launch(void* const* d_in, const int* in_sizes, int n_in,
                              void* d_out, int out_size)
{
    const float* x    = (const float*)d_in[0];  // [T,B,D]
    const float* h0   = (const float*)d_in[1];  // [B,H]
    const float* st   = (const float*)d_in[2];  // [B,H]
    const float* W_in = (const float*)d_in[3];  // [H,D]
    const float* b_in = (const float*)d_in[4];  // [H]
    const float* W_h  = (const float*)d_in[5];  // [H,H]
    const float* b_h  = (const float*)d_in[6];  // [H]
    const float* W_o  = (const float*)d_in[7];  // [O,H]
    const float* b_o  = (const float*)d_in[8];  // [O]
    float* out = (float*)d_out;

    float* Eptr = nullptr;
    float* hfin = nullptr;
    unsigned* grpptr = nullptr;
    cudaGetSymbolAddress((void**)&Eptr, g_E);
    cudaGetSymbolAddress((void**)&hfin, g_hfinal);
    cudaGetSymbolAddress((void**)&grpptr, g_grp);

    // reset group barrier counters (graph replays must see zeros)
    cudaMemsetAsync(grpptr, 0, 8 * 32 * sizeof(unsigned));

    // 0) h0 -> bf16 transport buffer
    h0_to_bf16<<<(BATCH * HID) / 256, 256>>>(h0);

    // 1) E = x @ W_in^T + b_in (bf16 3-term split, fp32 accumulate)
    {
        const int smem_bytes = 24576 * sizeof(unsigned);  // 96KB
        cudaFuncSetAttribute(egemm_bf16x3,
                             cudaFuncAttributeMaxDynamicSharedMemorySize, smem_bytes);
        dim3 grid(HID / 64, (T_STEPS * BATCH) / 128);
        egemm_bf16x3<<<grid, 256, smem_bytes>>>(x, W_in, b_in, Eptr);
    }

    // 2) Persistent recurrence (bf16 tensor cores, group barriers)
    {
        const int smem_bytes = (32768 + 4096) * sizeof(unsigned);  // 144KB
        cudaFuncSetAttribute(rnn_persistent,
                             cudaFuncAttributeMaxDynamicSharedMemorySize, smem_bytes);
        rnn_persistent<<<GRID_P, 256, smem_bytes>>>(W_h, b_h);
    }

    // 3) Head + output tuple
    finalize_kernel<<<BATCH, 128>>>(hfin, st, W_o, b_o, out);
}